// round 1
// baseline (speedup 1.0000x reference)
#include <cuda_runtime.h>
#include <math.h>
#include <float.h>

#define BB 8
#define NN 4096
#define KK 9
#define ROWS (BB*NN*KK)   /* 294912 */
#define NB1 256
#define NB3 512

// Scratch (allocation-free: __device__ globals)
__device__ float g_h1[ROWS*10];
__device__ float g_h2[ROWS*10];
__device__ float g_p1[NB1*20];
__device__ float g_p2[NB3*20];
__device__ float g_s1[20];   // mu[10], inv[10]
__device__ float g_s2[20];

__device__ __forceinline__ bool dless(float d1, int j1, float d2, int j2) {
    return d1 < d2 || (d1 == d2 && j1 < j2);
}

// ---------------------------------------------------------------------------
// Kernel 1: kNN top-10 + geometric features + linear1 + BN1 partial stats
// grid (NN/128, BB), block 128, dyn smem = NN*16 + 440
// ---------------------------------------------------------------------------
__global__ void knn_feat_kernel(const float* __restrict__ x,
                                const float* __restrict__ W1,
                                const float* __restrict__ b1) {
    extern __shared__ float4 sx[];
    float* sW = (float*)&sx[NN];   // 100 floats
    float* sb = sW + 100;          // 10 floats

    const int tid = threadIdx.x;
    const int b = blockIdx.y;
    const float* xb = x + (size_t)b * NN * 3;

    for (int j = tid; j < NN; j += blockDim.x) {
        float xx = xb[j*3+0], yy = xb[j*3+1], zz = xb[j*3+2];
        float w = fmaf(zz, zz, fmaf(yy, yy, xx*xx));
        sx[j] = make_float4(xx, yy, zz, w);
    }
    if (tid < 100) sW[tid] = W1[tid];
    if (tid < 10)  sb[tid] = b1[tid];
    __syncthreads();

    const int n = blockIdx.x * blockDim.x + tid;
    const float4 q = sx[n];
    const float qx = q.x, qy = q.y, qz = q.z, q2 = q.w;

    // top-10 (ascending), tie-break: lower index first (matches lax.top_k)
    float bd[10]; int bi[10];
    #pragma unroll
    for (int t = 0; t < 10; ++t) { bd[t] = FLT_MAX; bi[t] = 0x7fffffff; }

    #pragma unroll 4
    for (int j = 0; j < NN; ++j) {
        float4 c = sx[j];
        float dot = fmaf(qz, c.z, fmaf(qy, c.y, qx * c.x));
        // match reference: (x2n + x2m) - 2*dot, no fma contraction on combine
        float d = __fsub_rn(__fadd_rn(q2, c.w), __fmul_rn(2.0f, dot));
        if (dless(d, j, bd[9], bi[9])) {
            float cd = d; int cj = j;
            #pragma unroll
            for (int t = 0; t < 10; ++t) {
                if (dless(cd, cj, bd[t], bi[t])) {
                    float td = bd[t]; bd[t] = cd; cd = td;
                    int ti = bi[t]; bi[t] = cj; cj = ti;
                }
            }
        }
    }

    // rel vectors for neighbors 1..9 (drop position 0 = self), angles
    float rx[9], ry[9], rz[9], ph[9];
    #pragma unroll
    for (int e = 0; e < 9; ++e) {
        float4 c = sx[bi[e+1]];
        rx[e] = c.x - qx; ry[e] = c.y - qy; rz[e] = c.z - qz;
        ph[e] = atan2f(ry[e], rx[e]);
    }

    // stable ascending bubble sort on phi (matches stable jnp.argsort)
    #pragma unroll
    for (int p = 0; p < 8; ++p) {
        #pragma unroll
        for (int u = 0; u < 8; ++u) {
            if (ph[u+1] < ph[u]) {
                float t;
                t = ph[u]; ph[u] = ph[u+1]; ph[u+1] = t;
                t = rx[u]; rx[u] = rx[u+1]; rx[u+1] = t;
                t = ry[u]; ry[u] = ry[u+1]; ry[u+1] = t;
                t = rz[u]; rz[u] = rz[u+1]; rz[u+1] = t;
            }
        }
    }

    // geometry + linear1 + stat accumulation
    float ls[10], ls2[10];
    #pragma unroll
    for (int o = 0; o < 10; ++o) { ls[o] = 0.0f; ls2[o] = 0.0f; }
    float sgn = 1.0f;
    const int base = ((b * NN + n) * KK) * 10;

    #pragma unroll
    for (int e = 0; e < 9; ++e) {
        const int e2 = (e + 1 == 9) ? 0 : e + 1;
        float ax = rx[e],  ay = ry[e],  az = rz[e];
        float bx = rx[e2], by = ry[e2], bz = rz[e2];
        float cx = 0.5f * (ax + bx), cy = 0.5f * (ay + by), cz = 0.5f * (az + bz);
        float nx = ay*bz - az*by;
        float ny = az*bx - ax*bz;
        float nz = ax*by - ay*bx;
        float nnv = sqrtf(nx*nx + ny*ny + nz*nz);
        float ri = 1.0f / (nnv + 1e-6f);
        nx *= ri; ny *= ri; nz *= ri;
        if (e == 0) sgn = (nx > 0.0f) ? 1.0f : -1.0f;
        nx *= sgn; ny *= sgn; nz *= sgn;
        float pos = (nx*cx + ny*cy + nz*cz) / sqrtf(3.0f);
        float dv = ax*bx + ay*by + az*bz;
        float nA = sqrtf(ax*ax + ay*ay + az*az);
        float nB = sqrtf(bx*bx + by*by + bz*bz);
        float cv = dv / (nA * nB + 1e-8f);
        cv = fminf(1.0f, fmaxf(-1.0f, cv));
        float ang = acosf(cv);
        float f[10] = {cx, cy, cz, nx, ny, nz, pos, ang, nA, nB};
        #pragma unroll
        for (int o = 0; o < 10; ++o) {
            float h = sb[o];
            #pragma unroll
            for (int i = 0; i < 10; ++i) h = fmaf(f[i], sW[o*10+i], h);
            g_h1[base + e*10 + o] = h;
            ls[o] += h;
            ls2[o] = fmaf(h, h, ls2[o]);
        }
    }

    // block reduction of BN1 partials (reuse sx region after sync)
    __syncthreads();
    float* sred = (float*)sx;   // 4 warps * 20 floats
    const int lane = tid & 31, wid = tid >> 5;
    #pragma unroll
    for (int t = 0; t < 20; ++t) {
        float v = (t < 10) ? ls[t] : ls2[t-10];
        #pragma unroll
        for (int off = 16; off > 0; off >>= 1) v += __shfl_down_sync(0xffffffffu, v, off);
        if (lane == 0) sred[wid*20 + t] = v;
    }
    __syncthreads();
    if (tid < 20) {
        float s = 0.0f;
        const int nw = blockDim.x >> 5;
        for (int w = 0; w < nw; ++w) s += sred[w*20 + tid];
        g_p1[(blockIdx.y * gridDim.x + blockIdx.x) * 20 + tid] = s;
    }
}

// ---------------------------------------------------------------------------
// Stats reduce: partials -> mu, rsqrt(var + eps). <<<1,160>>>
// ---------------------------------------------------------------------------
__global__ void stats_kernel(int which) {
    const float* part = which ? g_p2 : g_p1;
    const int nb = which ? NB3 : NB1;
    float* stats = which ? g_s2 : g_s1;
    __shared__ double sdd[20][8];
    __shared__ float sd[20];
    const int tid = threadIdx.x;
    if (tid < 160) {
        const int col = tid >> 3, sl = tid & 7;
        double s = 0.0;
        for (int i = sl; i < nb; i += 8) s += (double)part[i*20 + col];
        sdd[col][sl] = s;
    }
    __syncthreads();
    if (tid < 20) {
        double s = 0.0;
        #pragma unroll
        for (int i = 0; i < 8; ++i) s += sdd[tid][i];
        sd[tid] = (float)(s / (double)ROWS);
    }
    __syncthreads();
    if (tid < 10) {
        float mu = sd[tid];
        float var = fmaxf(sd[tid+10] - mu*mu, 0.0f);
        stats[tid] = mu;
        stats[10+tid] = rsqrtf(var + 1e-5f);
    }
}

// ---------------------------------------------------------------------------
// Kernel 3: BN1 + ReLU + linear2 + BN2 partial stats. <<<NB3,256>>>
// ---------------------------------------------------------------------------
__global__ void mlp2_kernel(const float* __restrict__ g1v, const float* __restrict__ be1,
                            const float* __restrict__ W2, const float* __restrict__ b2) {
    __shared__ float sW[100], sb[10], smu[10], sinv[10], sg[10], sbe[10];
    __shared__ float sred[8*20];
    const int tid = threadIdx.x;
    if (tid < 100) sW[tid] = W2[tid];
    if (tid < 10) {
        sb[tid] = b2[tid]; smu[tid] = g_s1[tid]; sinv[tid] = g_s1[10+tid];
        sg[tid] = g1v[tid]; sbe[tid] = be1[tid];
    }
    __syncthreads();
    float ls[10], ls2[10];
    #pragma unroll
    for (int o = 0; o < 10; ++o) { ls[o] = 0.0f; ls2[o] = 0.0f; }
    const int stride = gridDim.x * blockDim.x;
    for (int r = blockIdx.x * blockDim.x + tid; r < ROWS; r += stride) {
        float a[10];
        #pragma unroll
        for (int i = 0; i < 10; ++i) {
            float h = g_h1[r*10 + i];
            h = ((h - smu[i]) * sinv[i]) * sg[i] + sbe[i];
            a[i] = fmaxf(h, 0.0f);
        }
        #pragma unroll
        for (int o = 0; o < 10; ++o) {
            float h = sb[o];
            #pragma unroll
            for (int i = 0; i < 10; ++i) h = fmaf(a[i], sW[o*10+i], h);
            g_h2[r*10 + o] = h;
            ls[o] += h;
            ls2[o] = fmaf(h, h, ls2[o]);
        }
    }
    const int lane = tid & 31, wid = tid >> 5;
    #pragma unroll
    for (int t = 0; t < 20; ++t) {
        float v = (t < 10) ? ls[t] : ls2[t-10];
        #pragma unroll
        for (int off = 16; off > 0; off >>= 1) v += __shfl_down_sync(0xffffffffu, v, off);
        if (lane == 0) sred[wid*20 + t] = v;
    }
    __syncthreads();
    if (tid < 20) {
        float s = 0.0f;
        #pragma unroll
        for (int w = 0; w < 8; ++w) s += sred[w*20 + tid];
        g_p2[blockIdx.x*20 + tid] = s;
    }
}

// ---------------------------------------------------------------------------
// Kernel 5: BN2 + ReLU + max over k. <<<BB*NN/256, 256>>>
// ---------------------------------------------------------------------------
__global__ void out_kernel(const float* __restrict__ g2v, const float* __restrict__ be2,
                           float* __restrict__ out) {
    __shared__ float smu[10], sinv[10], sg[10], sbe[10];
    const int tid = threadIdx.x;
    if (tid < 10) {
        smu[tid] = g_s2[tid]; sinv[tid] = g_s2[10+tid];
        sg[tid] = g2v[tid]; sbe[tid] = be2[tid];
    }
    __syncthreads();
    const int p = blockIdx.x * blockDim.x + tid;
    float m[10];
    #pragma unroll
    for (int o = 0; o < 10; ++o) m[o] = 0.0f;  // relu outputs are >= 0
    const int base = p * KK * 10;
    #pragma unroll
    for (int e = 0; e < 9; ++e) {
        #pragma unroll
        for (int o = 0; o < 10; ++o) {
            float h = g_h2[base + e*10 + o];
            float y = fmaxf(((h - smu[o]) * sinv[o]) * sg[o] + sbe[o], 0.0f);
            m[o] = fmaxf(m[o], y);
        }
    }
    #pragma unroll
    for (int o = 0; o < 10; ++o) out[p*10 + o] = m[o];
}

// ---------------------------------------------------------------------------
extern "C" void kernel_launch(void* const* d_in, const int* in_sizes, int n_in,
                              void* d_out, int out_size) {
    (void)in_sizes; (void)n_in; (void)out_size;
    const float* x   = (const float*)d_in[0];
    const float* W1  = (const float*)d_in[1];
    const float* b1  = (const float*)d_in[2];
    const float* g1  = (const float*)d_in[3];
    const float* be1 = (const float*)d_in[4];
    const float* W2  = (const float*)d_in[5];
    const float* b2  = (const float*)d_in[6];
    const float* g2  = (const float*)d_in[7];
    const float* be2 = (const float*)d_in[8];
    float* out = (float*)d_out;

    const int smem1 = NN * 16 + 110 * 4;
    cudaFuncSetAttribute(knn_feat_kernel, cudaFuncAttributeMaxDynamicSharedMemorySize, smem1);

    dim3 grid1(NN / 128, BB);
    knn_feat_kernel<<<grid1, 128, smem1>>>(x, W1, b1);
    stats_kernel<<<1, 160>>>(0);
    mlp2_kernel<<<NB3, 256>>>(g1, be1, W2, b2);
    stats_kernel<<<1, 160>>>(1);
    out_kernel<<<(BB*NN)/256, 256>>>(g2, be2, out);
}